// round 13
// baseline (speedup 1.0000x reference)
#include <cuda_runtime.h>
#include <math.h>

#define BPB 256            // blocks per batch; 1024 CTAs ~7/SM single wave
#define THREADS 256
#define NBATCH 4
#define NELEM (192*192*192)        // 7,077,888 per batch
#define NVEC  (NELEM/4)            // 1,769,472 float4 per batch
#define STRIDE (BPB * THREADS)
#define NITER (NVEC / STRIDE)      // exactly 27, no tail

__device__ float g_partials[NBATCH * BPB * 5];
__device__ unsigned int g_ticket[NBATCH];   // zero-init; reset by last block each run

__device__ __forceinline__ float warp_sum(float v) {
    #pragma unroll
    for (int o = 16; o > 0; o >>= 1)
        v += __shfl_xor_sync(0xFFFFFFFFu, v, o);
    return v;
}

__global__ __launch_bounds__(THREADS, 8)   // <=32 regs -> max resident warps
void ncc_fused(const float4* __restrict__ J4,   // y_pred
               const float4* __restrict__ I4,   // y_true
               float* __restrict__ out)
{
    const int b = blockIdx.y;
    const float4* __restrict__ Ib = I4 + (size_t)b * NVEC;
    const float4* __restrict__ Jb = J4 + (size_t)b * NVEC;

    float sI = 0.f, sJ = 0.f, sII = 0.f, sJJ = 0.f, sIJ = 0.f;

    const int base = blockIdx.x * THREADS + threadIdx.x;
    for (int k = 0; k < NITER; k++) {
        const int i = base + k * STRIDE;
        float4 a = Ib[i];
        float4 c = Jb[i];
        sI  += a.x + a.y + a.z + a.w;
        sJ  += c.x + c.y + c.z + c.w;
        sII += a.x*a.x + a.y*a.y + a.z*a.z + a.w*a.w;
        sJJ += c.x*c.x + c.y*c.y + c.z*c.z + c.w*c.w;
        sIJ += a.x*c.x + a.y*c.y + a.z*c.z + a.w*c.w;
    }

    // intra-warp reduce
    sI  = warp_sum(sI);
    sJ  = warp_sum(sJ);
    sII = warp_sum(sII);
    sJJ = warp_sum(sJJ);
    sIJ = warp_sum(sIJ);

    __shared__ float sm[5][THREADS / 32];
    const int lane = threadIdx.x & 31;
    const int wid  = threadIdx.x >> 5;
    if (lane == 0) {
        sm[0][wid] = sI;  sm[1][wid] = sJ;  sm[2][wid] = sII;
        sm[3][wid] = sJJ; sm[4][wid] = sIJ;
    }
    __syncthreads();

    __shared__ bool isLast;
    if (wid == 0) {
        const int nw = THREADS / 32;
        float v0 = (lane < nw) ? sm[0][lane] : 0.f;
        float v1 = (lane < nw) ? sm[1][lane] : 0.f;
        float v2 = (lane < nw) ? sm[2][lane] : 0.f;
        float v3 = (lane < nw) ? sm[3][lane] : 0.f;
        float v4 = (lane < nw) ? sm[4][lane] : 0.f;
        v0 = warp_sum(v0); v1 = warp_sum(v1); v2 = warp_sum(v2);
        v3 = warp_sum(v3); v4 = warp_sum(v4);
        if (lane == 0) {
            float* p = &g_partials[(b * BPB + blockIdx.x) * 5];
            p[0] = v0; p[1] = v1; p[2] = v2; p[3] = v3; p[4] = v4;
            __threadfence();
            unsigned int t = atomicAdd(&g_ticket[b], 1u);
            isLast = (t == BPB - 1);
        }
    }
    __syncthreads();

    if (!isLast) return;

    // ---- last block for this batch: exactly one round over BPB=256 partials ----
    {
        const float* p = &g_partials[(b * BPB + threadIdx.x) * 5];
        float tI  = p[0];
        float tJ  = p[1];
        float tII = p[2];
        float tJJ = p[3];
        float tIJ = p[4];

        tI  = warp_sum(tI);
        tJ  = warp_sum(tJ);
        tII = warp_sum(tII);
        tJJ = warp_sum(tJJ);
        tIJ = warp_sum(tIJ);

        __syncthreads();   // sm[][] reuse
        if (lane == 0) {
            sm[0][wid] = tI;  sm[1][wid] = tJ;  sm[2][wid] = tII;
            sm[3][wid] = tJJ; sm[4][wid] = tIJ;
        }
        __syncthreads();

        if (threadIdx.x == 0) {
            const int nw = THREADS / 32;
            float fI = 0.f, fJ = 0.f, fII = 0.f, fJJ = 0.f, fIJ = 0.f;
            for (int w = 0; w < nw; w++) {
                fI += sm[0][w]; fJ += sm[1][w]; fII += sm[2][w];
                fJJ += sm[3][w]; fIJ += sm[4][w];
            }
            const float n = (float)NELEM;
            float cross = fIJ - fI * fJ / n;
            float Ivar  = fII - fI * fI / n;
            float Jvar  = fJJ - fJ * fJ / n;
            out[b] = cross / (sqrtf(Ivar) * sqrtf(Jvar) + 1e-5f);
            g_ticket[b] = 0u;    // reset for next graph replay
        }
    }
}

extern "C" void kernel_launch(void* const* d_in, const int* in_sizes, int n_in,
                              void* d_out, int out_size)
{
    const float4* y_pred = (const float4*)d_in[0];  // Ji
    const float4* y_true = (const float4*)d_in[1];  // Ii
    float* out = (float*)d_out;

    dim3 grid(BPB, NBATCH);
    ncc_fused<<<grid, THREADS>>>(y_pred, y_true, out);
}

// round 14
// speedup vs baseline: 1.0057x; 1.0057x over previous
#include <cuda_runtime.h>
#include <math.h>

#define BPB 256            // blocks per batch; 1024 CTAs ~7/SM single wave
#define THREADS 256
#define NBATCH 4
#define NELEM (192*192*192)        // 7,077,888 per batch
#define NVEC  (NELEM/4)            // 1,769,472 float4 per batch
// NVEC / (BPB*THREADS) = 27 exactly -> no tail iteration

__device__ float g_partials[NBATCH * BPB * 5];
__device__ unsigned int g_ticket[NBATCH];   // zero-init; reset by last block each run

__device__ __forceinline__ float warp_sum(float v) {
    #pragma unroll
    for (int o = 16; o > 0; o >>= 1)
        v += __shfl_xor_sync(0xFFFFFFFFu, v, o);
    return v;
}

__global__ __launch_bounds__(THREADS, 8)   // <=32 regs -> max resident warps
void ncc_fused(const float4* __restrict__ J4,   // y_pred
               const float4* __restrict__ I4,   // y_true
               float* __restrict__ out)
{
    const int b = blockIdx.y;
    const float4* __restrict__ Ib = I4 + (size_t)b * NVEC;
    const float4* __restrict__ Jb = J4 + (size_t)b * NVEC;

    float sI = 0.f, sJ = 0.f, sII = 0.f, sJJ = 0.f, sIJ = 0.f;

    for (int i = blockIdx.x * THREADS + threadIdx.x; i < NVEC;
         i += BPB * THREADS) {
        float4 a = Ib[i];
        float4 c = Jb[i];
        sI  += a.x + a.y + a.z + a.w;
        sJ  += c.x + c.y + c.z + c.w;
        sII += a.x*a.x + a.y*a.y + a.z*a.z + a.w*a.w;
        sJJ += c.x*c.x + c.y*c.y + c.z*c.z + c.w*c.w;
        sIJ += a.x*c.x + a.y*c.y + a.z*c.z + a.w*c.w;
    }

    // intra-warp reduce
    sI  = warp_sum(sI);
    sJ  = warp_sum(sJ);
    sII = warp_sum(sII);
    sJJ = warp_sum(sJJ);
    sIJ = warp_sum(sIJ);

    __shared__ float sm[5][THREADS / 32];
    const int lane = threadIdx.x & 31;
    const int wid  = threadIdx.x >> 5;
    if (lane == 0) {
        sm[0][wid] = sI;  sm[1][wid] = sJ;  sm[2][wid] = sII;
        sm[3][wid] = sJJ; sm[4][wid] = sIJ;
    }
    __syncthreads();

    __shared__ bool isLast;
    if (wid == 0) {
        const int nw = THREADS / 32;
        float v0 = (lane < nw) ? sm[0][lane] : 0.f;
        float v1 = (lane < nw) ? sm[1][lane] : 0.f;
        float v2 = (lane < nw) ? sm[2][lane] : 0.f;
        float v3 = (lane < nw) ? sm[3][lane] : 0.f;
        float v4 = (lane < nw) ? sm[4][lane] : 0.f;
        v0 = warp_sum(v0); v1 = warp_sum(v1); v2 = warp_sum(v2);
        v3 = warp_sum(v3); v4 = warp_sum(v4);
        if (lane == 0) {
            float* p = &g_partials[(b * BPB + blockIdx.x) * 5];
            p[0] = v0; p[1] = v1; p[2] = v2; p[3] = v3; p[4] = v4;
            __threadfence();
            unsigned int t = atomicAdd(&g_ticket[b], 1u);
            isLast = (t == BPB - 1);
        }
    }
    __syncthreads();

    if (!isLast) return;

    // ---- last block for this batch: exactly one round over BPB=256 partials ----
    {
        const float* p = &g_partials[(b * BPB + threadIdx.x) * 5];
        float tI  = p[0];
        float tJ  = p[1];
        float tII = p[2];
        float tJJ = p[3];
        float tIJ = p[4];

        tI  = warp_sum(tI);
        tJ  = warp_sum(tJ);
        tII = warp_sum(tII);
        tJJ = warp_sum(tJJ);
        tIJ = warp_sum(tIJ);

        __syncthreads();   // sm[][] reuse
        if (lane == 0) {
            sm[0][wid] = tI;  sm[1][wid] = tJ;  sm[2][wid] = tII;
            sm[3][wid] = tJJ; sm[4][wid] = tIJ;
        }
        __syncthreads();

        if (threadIdx.x == 0) {
            const int nw = THREADS / 32;
            float fI = 0.f, fJ = 0.f, fII = 0.f, fJJ = 0.f, fIJ = 0.f;
            for (int w = 0; w < nw; w++) {
                fI += sm[0][w]; fJ += sm[1][w]; fII += sm[2][w];
                fJJ += sm[3][w]; fIJ += sm[4][w];
            }
            const float n = (float)NELEM;
            float cross = fIJ - fI * fJ / n;
            float Ivar  = fII - fI * fI / n;
            float Jvar  = fJJ - fJ * fJ / n;
            out[b] = cross / (sqrtf(Ivar) * sqrtf(Jvar) + 1e-5f);
            g_ticket[b] = 0u;    // reset for next graph replay
        }
    }
}

extern "C" void kernel_launch(void* const* d_in, const int* in_sizes, int n_in,
                              void* d_out, int out_size)
{
    const float4* y_pred = (const float4*)d_in[0];  // Ji
    const float4* y_true = (const float4*)d_in[1];  // Ii
    float* out = (float*)d_out;

    dim3 grid(BPB, NBATCH);
    ncc_fused<<<grid, THREADS>>>(y_pred, y_true, out);
}